// round 3
// baseline (speedup 1.0000x reference)
#include <cuda_runtime.h>
#include <math.h>

// ----------------------------------------------------------------------------
// QuantumBranch, fully fused single kernel.
// expz0(t) for fixed theta is EXACTLY a degree-12 trig polynomial in (pi*t).
// Every block independently (and identically):
//   1) 25 fp32 circuit evaluations at t_m = 2m/25   (25 threads)
//   2) exact real-DFT inversion -> 25 harmonic coefficients
//   3) 513 endpoint (f, f') evaluations -> 512-interval Hermite cubic table
//      stored SoA in shared memory (c0..c3)
//   4) grid-stride float4 main loop: 4x LDS.32 + 3 FMA per element
// Spline error ~ (12*pi)^4 / (384*512^4) ~ 8e-8  << 1e-3 tolerance.
// ----------------------------------------------------------------------------

#define NSAMP 25
#define NHARM 12
#define TBL   512
#define THREADS 256
#define PI_F  3.14159265358979323846f

struct cf { float re, im; };

__device__ __forceinline__ void gate1q(cf* s, int wire,
    float u00r, float u00i, float u01r, float u01i,
    float u10r, float u10i, float u11r, float u11i)
{
    const int str = 4 >> wire;
    #pragma unroll
    for (int k = 0; k < 8; k++) {
        if (k & str) continue;
        cf a = s[k], b = s[k + str];
        s[k].re       = u00r*a.re - u00i*a.im + u01r*b.re - u01i*b.im;
        s[k].im       = u00r*a.im + u00i*a.re + u01r*b.im + u01i*b.re;
        s[k + str].re = u10r*a.re - u10i*a.im + u11r*b.re - u11i*b.im;
        s[k + str].im = u10r*a.im + u10i*a.re + u11r*b.im + u11i*b.re;
    }
}

__device__ __forceinline__ void cnot(cf* s, int ctrl, int tgt)
{
    const int sc = 4 >> ctrl, st = 4 >> tgt;
    #pragma unroll
    for (int k = 0; k < 8; k++) {
        if (!(k & sc) || (k & st)) continue;
        cf tmp = s[k]; s[k] = s[k + st]; s[k + st] = tmp;
    }
}

__device__ void ansatz(cf* s, const float* th)
{
    #pragma unroll
    for (int i = 0; i < 3; i++) {
        float a = th[i*3 + 0];
        float c, z; __sincosf(0.5f*a, &z, &c);
        gate1q(s, i, c, -z, 0.f, 0.f, 0.f, 0.f, c, z);          // RZ
        a = th[i*3 + 1];
        __sincosf(0.5f*a, &z, &c);
        gate1q(s, i, c, 0.f, 0.f, -z, 0.f, -z, c, 0.f);         // RX
        a = th[i*3 + 2];
        __sincosf(0.5f*a, &z, &c);
        gate1q(s, i, c, -z, 0.f, 0.f, 0.f, 0.f, c, z);          // RZ
    }
    cnot(s, 0, 1); cnot(s, 1, 2); cnot(s, 2, 0);
}

__device__ void feature(cf* s, float t)
{
    #pragma unroll
    for (int i = 0; i < 3; i++) {
        float c, z;
        sincospif(0.5f * t * (float)(i + 1), &z, &c);
        gate1q(s, i, c, 0.f, -z, 0.f, z, 0.f, c, 0.f);          // RY
    }
}

__device__ float eval_circuit(const float* theta, float t)
{
    cf s[8];
    #pragma unroll
    for (int k = 0; k < 8; k++) { s[k].re = 0.f; s[k].im = 0.f; }
    s[0].re = 1.f;
    ansatz(s, theta);
    feature(s, t);
    ansatz(s, theta + 9);
    feature(s, t);
    ansatz(s, theta + 18);
    float e = 0.f;
    #pragma unroll
    for (int k = 0; k < 8; k++) {
        float p = s[k].re*s[k].re + s[k].im*s[k].im;
        e += (k < 4) ? p : -p;   // Z on qubit 0 (bit value 4)
    }
    return e;
}

__global__ void __launch_bounds__(THREADS)
fused_kernel(const float* __restrict__ theta,
             const float* __restrict__ t,
             float* __restrict__ out, int n)
{
    __shared__ float fs[NSAMP];
    __shared__ float ca[NHARM + 1], cb[NHARM + 1];
    __shared__ float fv[TBL + 1], Dv[TBL + 1];
    __shared__ float c0[TBL], c1[TBL], c2[TBL], c3[TBL];

    const int tid = threadIdx.x;

    // ---- 1) circuit samples -------------------------------------------------
    if (tid < NSAMP)
        fs[tid] = eval_circuit(theta, 2.0f * (float)tid / 25.0f);
    __syncthreads();

    // ---- 2) exact real DFT on 25 samples ------------------------------------
    if (tid < NSAMP) {
        float sum = 0.f;
        if (tid == 0) {
            for (int m = 0; m < NSAMP; m++) sum += fs[m];
            ca[0] = sum * (1.0f / 25.0f);
            cb[0] = 0.f;
        } else if (tid <= NHARM) {
            for (int m = 0; m < NSAMP; m++) {
                int r = (tid * m) % 25;
                float c, s; sincospif(2.0f * (float)r / 25.0f, &s, &c);
                sum += fs[m] * c;
            }
            ca[tid] = sum * (2.0f / 25.0f);
        } else {
            int k = tid - NHARM;
            for (int m = 0; m < NSAMP; m++) {
                int r = (k * m) % 25;
                float c, s; sincospif(2.0f * (float)r / 25.0f, &s, &c);
                sum += fs[m] * s;
            }
            cb[k] = sum * (2.0f / 25.0f);
        }
    }
    __syncthreads();

    // ---- 3a) endpoint values f(t_e) and scaled derivatives f'(t_e)*h --------
    for (int e = tid; e <= TBL; e += THREADS) {
        float tt = (float)e * (1.0f / (float)TBL);
        float c1v, s1v; sincospif(tt, &s1v, &c1v);   // cos(pi t), sin(pi t)
        float f = fmaf(ca[1], c1v, ca[0]);
        f = fmaf(cb[1], s1v, f);
        float g = cb[1]*c1v - ca[1]*s1v;
        const float twoc = c1v + c1v;
        float ckm = 1.f, ck = c1v, skm = 0.f, sk = s1v;
        #pragma unroll
        for (int k = 2; k <= NHARM; k++) {
            float cn = fmaf(twoc, ck, -ckm);
            float sn = fmaf(twoc, sk, -skm);
            f = fmaf(ca[k], cn, f);
            f = fmaf(cb[k], sn, f);
            g = fmaf((float)k, cb[k]*cn - ca[k]*sn, g);
            ckm = ck; ck = cn; skm = sk; sk = sn;
        }
        fv[e] = f;
        Dv[e] = g * (PI_F / (float)TBL);
    }
    __syncthreads();

    // ---- 3b) Hermite cubic power-basis coefficients (SoA) --------------------
    for (int i = tid; i < TBL; i += THREADS) {
        float f0 = fv[i], f1 = fv[i + 1];
        float D0 = Dv[i], D1 = Dv[i + 1];
        c0[i] = f0;
        c1[i] = D0;
        c2[i] = 3.f*(f1 - f0) - 2.f*D0 - D1;
        c3[i] = 2.f*(f0 - f1) + D0 + D1;
    }
    __syncthreads();

    // ---- 4) main loop ---------------------------------------------------------
    const int nvec = n >> 2;
    const int stride = gridDim.x * blockDim.x;
    for (int v = blockIdx.x * blockDim.x + tid; v < nvec; v += stride) {
        float4 tv = __ldg(reinterpret_cast<const float4*>(t) + v);
        float4 ov;
        {
            float x = tv.x * (float)TBL;
            int i = min((int)x, TBL - 1);
            float u = x - (float)i;
            ov.x = fmaf(fmaf(fmaf(c3[i], u, c2[i]), u, c1[i]), u, c0[i]);
        }
        {
            float x = tv.y * (float)TBL;
            int i = min((int)x, TBL - 1);
            float u = x - (float)i;
            ov.y = fmaf(fmaf(fmaf(c3[i], u, c2[i]), u, c1[i]), u, c0[i]);
        }
        {
            float x = tv.z * (float)TBL;
            int i = min((int)x, TBL - 1);
            float u = x - (float)i;
            ov.z = fmaf(fmaf(fmaf(c3[i], u, c2[i]), u, c1[i]), u, c0[i]);
        }
        {
            float x = tv.w * (float)TBL;
            int i = min((int)x, TBL - 1);
            float u = x - (float)i;
            ov.w = fmaf(fmaf(fmaf(c3[i], u, c2[i]), u, c1[i]), u, c0[i]);
        }
        reinterpret_cast<float4*>(out)[v] = ov;
    }
    // tail (n not multiple of 4)
    for (int i = (nvec << 2) + blockIdx.x * blockDim.x + tid; i < n; i += stride) {
        float x = t[i] * (float)TBL;
        int j = min((int)x, TBL - 1);
        float u = x - (float)j;
        out[i] = fmaf(fmaf(fmaf(c3[j], u, c2[j]), u, c1[j]), u, c0[j]);
    }
}

extern "C" void kernel_launch(void* const* d_in, const int* in_sizes, int n_in,
                              void* d_out, int out_size)
{
    const float* t;
    const float* theta;
    if (n_in >= 2 && in_sizes[0] == 27 && in_sizes[1] != 27) {
        theta = (const float*)d_in[0];
        t     = (const float*)d_in[1];
    } else {
        t     = (const float*)d_in[0];
        theta = (const float*)d_in[1];
    }
    float* out = (float*)d_out;
    const int n = out_size;

    // One wave on 152 SMs at 8 blocks/SM (12.3 KB smem, 2048 threads/SM).
    fused_kernel<<<1216, THREADS>>>(theta, t, out, n);
}

// round 4
// speedup vs baseline: 1.4307x; 1.4307x over previous
#include <cuda_runtime.h>
#include <math.h>

// ----------------------------------------------------------------------------
// QuantumBranch, fused single kernel (round 4).
// expz0(t) for fixed theta is EXACTLY a degree-12 trig polynomial in (pi*t).
// Every block independently builds the same 256-interval Hermite-cubic table
// in ITS OWN shared memory (fast __sincosf trig only -- libm sincospif was the
// round-3 regression: ~1-2k cycles/call on the critical path), then runs the
// grid-stride float4 main loop: 4x LDS.32 + 3 FMA per element.
// Spline error ~ (12*pi)^4/(384*256^4) ~ 1.3e-6  << 1e-3 tolerance.
// ----------------------------------------------------------------------------

#define NSAMP 25
#define NHARM 12
#define TBL   256
#define THREADS 256
#define PI_F  3.14159265358979323846f
#define TWO_PI_F 6.28318530717958647692f

struct cf { float re, im; };

__device__ __forceinline__ void gate1q(cf* s, int wire,
    float u00r, float u00i, float u01r, float u01i,
    float u10r, float u10i, float u11r, float u11i)
{
    const int str = 4 >> wire;
    #pragma unroll
    for (int k = 0; k < 8; k++) {
        if (k & str) continue;
        cf a = s[k], b = s[k + str];
        s[k].re       = u00r*a.re - u00i*a.im + u01r*b.re - u01i*b.im;
        s[k].im       = u00r*a.im + u00i*a.re + u01r*b.im + u01i*b.re;
        s[k + str].re = u10r*a.re - u10i*a.im + u11r*b.re - u11i*b.im;
        s[k + str].im = u10r*a.im + u10i*a.re + u11r*b.im + u11i*b.re;
    }
}

__device__ __forceinline__ void cnot(cf* s, int ctrl, int tgt)
{
    const int sc = 4 >> ctrl, st = 4 >> tgt;
    #pragma unroll
    for (int k = 0; k < 8; k++) {
        if (!(k & sc) || (k & st)) continue;
        cf tmp = s[k]; s[k] = s[k + st]; s[k + st] = tmp;
    }
}

__device__ void ansatz(cf* s, const float* th)
{
    #pragma unroll
    for (int i = 0; i < 3; i++) {
        float a = th[i*3 + 0];
        float c, z; __sincosf(0.5f*a, &z, &c);
        gate1q(s, i, c, -z, 0.f, 0.f, 0.f, 0.f, c, z);          // RZ
        a = th[i*3 + 1];
        __sincosf(0.5f*a, &z, &c);
        gate1q(s, i, c, 0.f, 0.f, -z, 0.f, -z, c, 0.f);         // RX
        a = th[i*3 + 2];
        __sincosf(0.5f*a, &z, &c);
        gate1q(s, i, c, -z, 0.f, 0.f, 0.f, 0.f, c, z);          // RZ
    }
    cnot(s, 0, 1); cnot(s, 1, 2); cnot(s, 2, 0);
}

__device__ void feature(cf* s, float t)
{
    #pragma unroll
    for (int i = 0; i < 3; i++) {
        float c, z;
        __sincosf(0.5f * PI_F * t * (float)(i + 1), &z, &c);
        gate1q(s, i, c, 0.f, -z, 0.f, z, 0.f, c, 0.f);          // RY
    }
}

__device__ float eval_circuit(const float* theta, float t)
{
    cf s[8];
    #pragma unroll
    for (int k = 0; k < 8; k++) { s[k].re = 0.f; s[k].im = 0.f; }
    s[0].re = 1.f;
    ansatz(s, theta);
    feature(s, t);
    ansatz(s, theta + 9);
    feature(s, t);
    ansatz(s, theta + 18);
    float e = 0.f;
    #pragma unroll
    for (int k = 0; k < 8; k++) {
        float p = s[k].re*s[k].re + s[k].im*s[k].im;
        e += (k < 4) ? p : -p;   // Z on qubit 0 (bit value 4)
    }
    return e;
}

__global__ void __launch_bounds__(THREADS)
fused_kernel(const float* __restrict__ theta,
             const float* __restrict__ t,
             float* __restrict__ out, int n)
{
    __shared__ float fs[NSAMP];
    __shared__ float ca[NHARM + 1], cb[NHARM + 1];
    __shared__ float fv[TBL + 1], Dv[TBL + 1];
    __shared__ float c0[TBL], c1s[TBL], c2[TBL], c3[TBL];

    const int tid = threadIdx.x;

    // ---- 1) circuit samples (25 threads, fast trig only) ---------------------
    if (tid < NSAMP)
        fs[tid] = eval_circuit(theta, 2.0f * (float)tid / 25.0f);
    __syncthreads();

    // ---- 2) exact real DFT on 25 samples (fast trig twiddles) ----------------
    if (tid < NSAMP) {
        float sum = 0.f;
        if (tid == 0) {
            for (int m = 0; m < NSAMP; m++) sum += fs[m];
            ca[0] = sum * (1.0f / 25.0f);
            cb[0] = 0.f;
        } else if (tid <= NHARM) {
            for (int m = 0; m < NSAMP; m++) {
                int r = (tid * m) % 25;
                float c, s; __sincosf(TWO_PI_F * (float)r * (1.0f/25.0f), &s, &c);
                sum += fs[m] * c;
            }
            ca[tid] = sum * (2.0f / 25.0f);
        } else {
            int k = tid - NHARM;
            for (int m = 0; m < NSAMP; m++) {
                int r = (k * m) % 25;
                float c, s; __sincosf(TWO_PI_F * (float)r * (1.0f/25.0f), &s, &c);
                sum += fs[m] * s;
            }
            cb[k] = sum * (2.0f / 25.0f);
        }
    }
    __syncthreads();

    // ---- 3a) endpoint values f(t_e) and scaled derivatives f'(t_e)*h ---------
    for (int e = tid; e <= TBL; e += THREADS) {
        float tt = (float)e * (1.0f / (float)TBL);
        float c1v, s1v; __sincosf(PI_F * tt, &s1v, &c1v);
        float f = fmaf(ca[1], c1v, ca[0]);
        f = fmaf(cb[1], s1v, f);
        float g = cb[1]*c1v - ca[1]*s1v;
        const float twoc = c1v + c1v;
        float ckm = 1.f, ck = c1v, skm = 0.f, sk = s1v;
        #pragma unroll
        for (int k = 2; k <= NHARM; k++) {
            float cn = fmaf(twoc, ck, -ckm);
            float sn = fmaf(twoc, sk, -skm);
            f = fmaf(ca[k], cn, f);
            f = fmaf(cb[k], sn, f);
            g = fmaf((float)k, cb[k]*cn - ca[k]*sn, g);
            ckm = ck; ck = cn; skm = sk; sk = sn;
        }
        fv[e] = f;
        Dv[e] = g * (PI_F / (float)TBL);
    }
    __syncthreads();

    // ---- 3b) Hermite cubic power-basis coefficients (SoA) ---------------------
    for (int i = tid; i < TBL; i += THREADS) {
        float f0 = fv[i], f1 = fv[i + 1];
        float D0 = Dv[i], D1 = Dv[i + 1];
        c0[i]  = f0;
        c1s[i] = D0;
        c2[i]  = 3.f*(f1 - f0) - 2.f*D0 - D1;
        c3[i]  = 2.f*(f0 - f1) + D0 + D1;
    }
    __syncthreads();

    // ---- 4) main loop ----------------------------------------------------------
    const int nvec = n >> 2;
    const int stride = gridDim.x * blockDim.x;
    for (int v = blockIdx.x * blockDim.x + tid; v < nvec; v += stride) {
        float4 tv = __ldg(reinterpret_cast<const float4*>(t) + v);
        float4 ov;
        {
            float x = tv.x * (float)TBL;
            int i = min((int)x, TBL - 1);
            float u = x - (float)i;
            ov.x = fmaf(fmaf(fmaf(c3[i], u, c2[i]), u, c1s[i]), u, c0[i]);
        }
        {
            float x = tv.y * (float)TBL;
            int i = min((int)x, TBL - 1);
            float u = x - (float)i;
            ov.y = fmaf(fmaf(fmaf(c3[i], u, c2[i]), u, c1s[i]), u, c0[i]);
        }
        {
            float x = tv.z * (float)TBL;
            int i = min((int)x, TBL - 1);
            float u = x - (float)i;
            ov.z = fmaf(fmaf(fmaf(c3[i], u, c2[i]), u, c1s[i]), u, c0[i]);
        }
        {
            float x = tv.w * (float)TBL;
            int i = min((int)x, TBL - 1);
            float u = x - (float)i;
            ov.w = fmaf(fmaf(fmaf(c3[i], u, c2[i]), u, c1s[i]), u, c0[i]);
        }
        reinterpret_cast<float4*>(out)[v] = ov;
    }
    // tail (n not multiple of 4)
    for (int i = (nvec << 2) + blockIdx.x * blockDim.x + tid; i < n; i += stride) {
        float x = t[i] * (float)TBL;
        int j = min((int)x, TBL - 1);
        float u = x - (float)j;
        out[i] = fmaf(fmaf(fmaf(c3[j], u, c2[j]), u, c1s[j]), u, c0[j]);
    }
}

extern "C" void kernel_launch(void* const* d_in, const int* in_sizes, int n_in,
                              void* d_out, int out_size)
{
    const float* t;
    const float* theta;
    if (n_in >= 2 && in_sizes[0] == 27 && in_sizes[1] != 27) {
        theta = (const float*)d_in[0];
        t     = (const float*)d_in[1];
    } else {
        t     = (const float*)d_in[0];
        theta = (const float*)d_in[1];
    }
    float* out = (float*)d_out;
    const int n = out_size;

    // One wave: 152 SMs x 8 resident blocks (6.2 KB smem, 2048 threads/SM).
    fused_kernel<<<1216, THREADS>>>(theta, t, out, n);
}